// round 13
// baseline (speedup 1.0000x reference)
#include <cuda_runtime.h>
#include <math.h>
#include <stdint.h>

// Problem constants (fixed by the dataset)
#define Bv 16
#define Tv 3072
#define Dv 256
#define GHv 32
#define GWv 32
#define Gv 1024
#define BT (Bv * Tv)          // 49152

// Output layout: concat of [som_z (BT*Dv)] [q (BT*Gv)] [bmu (BT)] [k_coord (BT*2)]
#define OFF_Q   ((size_t)BT * Dv)
#define OFF_BMU (OFF_Q + (size_t)BT * Gv)
#define OFF_KC  (OFF_BMU + (size_t)BT)

// Exact-argmin refinement margin (dist units) and candidate cap.
#define REFINE_MARGIN 1.5e-2f
#define MAX_CAND 64

// GEMM tiling: BM=128, BN=128, K chunks of 32
#define KCH 32
#define NCHUNK (Dv / KCH)      // 8
#define NTILE (Gv / 128)       // 8 col-tiles

// Scratch (static device allocation — allowed; no cudaMalloc)
__device__ float    g_wz[(size_t)BT * Dv];    // weighted z, fp32 (refinement)
__device__ uint32_t g_wzh[(size_t)BT * 128];  // weighted z, bf16x2 kpairs (GEMM A)
__device__ uint32_t g_ndh[(size_t)Gv * 128];  // nodes, bf16x2 kpairs (GEMM B)
__device__ float    g_rown[BT];               // ||wz_row||^2
__device__ float    g_nn[Gv];                 // ||node||^2
__device__ float    g_psum[(size_t)BT * NTILE];              // per-tile row sums of u
__device__ unsigned long long g_pkey[(size_t)BT * NTILE];    // per-tile packed max keys

// ---------------------------------------------------------------------------
// helpers
// ---------------------------------------------------------------------------
__device__ __forceinline__ uint32_t bfpack(float lo, float hi) {
    uint32_t r;
    asm("cvt.rn.bf16x2.f32 %0, %1, %2;" : "=r"(r) : "f"(hi), "f"(lo));
    return r;
}

__device__ __forceinline__ void mma16(float* c, const uint32_t* a,
                                      uint32_t b0, uint32_t b1) {
    asm volatile(
        "mma.sync.aligned.m16n8k16.row.col.f32.bf16.bf16.f32 "
        "{%0,%1,%2,%3}, {%4,%5,%6,%7}, {%8,%9}, {%0,%1,%2,%3};"
        : "+f"(c[0]), "+f"(c[1]), "+f"(c[2]), "+f"(c[3])
        : "r"(a[0]), "r"(a[1]), "r"(a[2]), "r"(a[3]), "r"(b0), "r"(b1));
}

// Fragment-major word index for A (128 rows x 16 kpairs per chunk).
__device__ __forceinline__ int aIdx(int row, int p) {
    int wm = row >> 5, mi = (row >> 4) & 1, hi = (row >> 3) & 1, g4 = row & 7;
    int kk = p >> 3, w8 = p & 7, tg = w8 & 3, poff = w8 >> 2;
    return (((wm * 2 + mi) * 2 + kk) * 128) + g4 * 16 + tg * 4 + poff * 2 + hi;
}

// Fragment-major word index for B (128 n x 16 kpairs per chunk).
__device__ __forceinline__ int bIdx(int n, int p) {
    int wn = n >> 5, ni = (n >> 3) & 3, g4 = n & 7;
    int nh = ni >> 1, nl = ni & 1;
    int kk = p >> 3, w8 = p & 7, tg = w8 & 3, b01 = w8 >> 2;
    return ((wn * 2 + kk) * 256) + nh * 128 + g4 * 16 + tg * 4 + nl * 2 + b01;
}

// pack (u, global col) so that uint64 max == (max u, then lowest col)
__device__ __forceinline__ unsigned long long ukey(float u, int col) {
    return ((unsigned long long)__float_as_uint(u) << 32)
         | (unsigned long long)(uint32_t)(Gv - 1 - col);
}

// ---------------------------------------------------------------------------
// K0a: node norms + bf16 pack. 128 threads per node.
// ---------------------------------------------------------------------------
__global__ __launch_bounds__(128) void k_node_norm(const float* __restrict__ nodes) {
    int g = blockIdx.x;
    int tid = threadIdx.x;
    int lane = tid & 31, warp = tid >> 5;
    float2 v = ((const float2*)(nodes + (size_t)g * Dv))[tid];
    g_ndh[(size_t)g * 128 + tid] = bfpack(v.x, v.y);
    float s = v.x * v.x + v.y * v.y;
#pragma unroll
    for (int off = 16; off > 0; off >>= 1)
        s += __shfl_xor_sync(0xFFFFFFFFu, s, off);
    __shared__ float sw[4];
    if (lane == 0) sw[warp] = s;
    __syncthreads();
    if (tid == 0) g_nn[g] = (sw[0] + sw[1]) + (sw[2] + sw[3]);
}

// ---------------------------------------------------------------------------
// K0b: warp-per-row prep. wz (fp32 + bf16 pack) + row norms.
// ---------------------------------------------------------------------------
__global__ __launch_bounds__(256) void k_prep(const float* __restrict__ z,
                                              const float* __restrict__ mask) {
    int warp = threadIdx.x >> 5, lane = threadIdx.x & 31;
    int r = blockIdx.x * 8 + warp;
    float tw = 0.f;
    if (lane == 0) {
        int t = r % Tv;
        tw = powf(0.999f, (float)(Tv - 1 - t));
    }
    tw = __shfl_sync(0xFFFFFFFFu, tw, 0);
    float m = mask[r];
    const float* zp = z + (size_t)r * Dv + lane * 8;
    float* wp = g_wz + (size_t)r * Dv + lane * 8;
    float4 a = *(const float4*)zp;
    float4 b = *(const float4*)(zp + 4);
    a.x = (a.x * tw) * m; a.y = (a.y * tw) * m; a.z = (a.z * tw) * m; a.w = (a.w * tw) * m;
    b.x = (b.x * tw) * m; b.y = (b.y * tw) * m; b.z = (b.z * tw) * m; b.w = (b.w * tw) * m;
    *(float4*)wp = a;
    *(float4*)(wp + 4) = b;
    uint4 h;
    h.x = bfpack(a.x, a.y); h.y = bfpack(a.z, a.w);
    h.z = bfpack(b.x, b.y); h.w = bfpack(b.z, b.w);
    *(uint4*)(g_wzh + (size_t)r * 128 + lane * 4) = h;
    float s = a.x * a.x + a.y * a.y + a.z * a.z + a.w * a.w
            + b.x * b.x + b.y * b.y + b.z * b.z + b.w * b.w;
#pragma unroll
    for (int off = 16; off > 0; off >>= 1)
        s += __shfl_xor_sync(0xFFFFFFFFu, s, off);
    if (lane == 0) g_rown[r] = s;
}

// ---------------------------------------------------------------------------
// K1: bf16 mma.sync m16n8k16 GEMM on pre-packed operands, fragment-major
// smem, double-buffered. BM=128, BN=128, 512 threads (4M x 4N warps).
// grid = (BT/128, Gv/128), row-tile FAST (contiguous q writes).
// Epilogue: writes unnormalized u AND per-(row, col-tile) partial sum +
// packed argmax key, so k_row needs no block-wide reductions.
// ---------------------------------------------------------------------------
__global__ __launch_bounds__(512, 2) void k_gemm_bf(float* __restrict__ out) {
    __shared__ uint32_t sA[2][2048];
    __shared__ uint32_t sB[2][2048];
    __shared__ float s_rn[128];
    __shared__ float s_nn[128];
    __shared__ float s_ps[4 * 128];
    __shared__ unsigned long long s_pk[4 * 128];

    int tid = threadIdx.x;
    int lane = tid & 31, wid = tid >> 5;
    int g4 = lane >> 2, tg = lane & 3;
    int wm = wid & 3, wn = wid >> 2;
    int rowBase = blockIdx.x * 128;    // fast axis
    int colBase = blockIdx.y * 128;
    int ct = blockIdx.y;

    int lrow = tid >> 2;               // 0..127
    int s4 = (tid & 3) * 4;

    const uint32_t* Ag = g_wzh + (size_t)(rowBase + lrow) * 128 + s4;
    const uint32_t* Bg = g_ndh + (size_t)(colBase + lrow) * 128 + s4;

    int aI[4], bI[4];
#pragma unroll
    for (int j = 0; j < 4; j++) {
        aI[j] = aIdx(lrow, s4 + j);
        bI[j] = bIdx(lrow, s4 + j);
    }

    float acc[2][4][4];
#pragma unroll
    for (int mi = 0; mi < 2; mi++)
#pragma unroll
        for (int ni = 0; ni < 4; ni++)
#pragma unroll
            for (int k = 0; k < 4; k++) acc[mi][ni][k] = 0.f;

    uint4 pa = *(const uint4*)(Ag);
    uint4 pb = *(const uint4*)(Bg);

    {
        const uint32_t* aw = (const uint32_t*)&pa;
        const uint32_t* bw = (const uint32_t*)&pb;
#pragma unroll
        for (int j = 0; j < 4; j++) { sA[0][aI[j]] = aw[j]; sB[0][bI[j]] = bw[j]; }
    }
    __syncthreads();

    for (int ch = 0; ch < NCHUNK; ch++) {
        int cur = ch & 1;
        if (ch + 1 < NCHUNK) {
            pa = *(const uint4*)(Ag + (ch + 1) * 16);
            pb = *(const uint4*)(Bg + (ch + 1) * 16);
        }

#pragma unroll
        for (int kk = 0; kk < 2; kk++) {
            uint4 af[2], bv[2];
#pragma unroll
            for (int mi = 0; mi < 2; mi++)
                af[mi] = *(const uint4*)&sA[cur][((wm * 2 + mi) * 2 + kk) * 128 + g4 * 16 + tg * 4];
#pragma unroll
            for (int nh = 0; nh < 2; nh++)
                bv[nh] = *(const uint4*)&sB[cur][(wn * 2 + kk) * 256 + nh * 128 + g4 * 16 + tg * 4];
#pragma unroll
            for (int mi = 0; mi < 2; mi++) {
                const uint32_t* ar = (const uint32_t*)&af[mi];
                mma16(acc[mi][0], ar, bv[0].x, bv[0].y);
                mma16(acc[mi][1], ar, bv[0].z, bv[0].w);
                mma16(acc[mi][2], ar, bv[1].x, bv[1].y);
                mma16(acc[mi][3], ar, bv[1].z, bv[1].w);
            }
        }

        if (ch + 1 < NCHUNK) {
            int nb = 1 - cur;
            const uint32_t* aw = (const uint32_t*)&pa;
            const uint32_t* bw = (const uint32_t*)&pb;
#pragma unroll
            for (int j = 0; j < 4; j++) { sA[nb][aI[j]] = aw[j]; sB[nb][bI[j]] = bw[j]; }
            __syncthreads();
        }
    }

    if (tid < 128) {
        s_rn[tid] = g_rown[rowBase + tid];
        s_nn[tid] = g_nn[colBase + tid];
    }
    __syncthreads();

    float* q = out + OFF_Q;
#pragma unroll
    for (int mi = 0; mi < 2; mi++) {
#pragma unroll
        for (int h = 0; h < 2; h++) {
            int r = wm * 32 + mi * 16 + g4 + h * 8;
            float rn = s_rn[r];
            size_t grow = (size_t)(rowBase + r) * Gv + colBase;
            float rsum = 0.f;
            unsigned long long rkey = 0ull;
#pragma unroll
            for (int ni = 0; ni < 4; ni++) {
                int c = wn * 32 + ni * 8 + tg * 2;
                float c0 = acc[mi][ni][h * 2 + 0];
                float c1 = acc[mi][ni][h * 2 + 1];
                float d20 = fmaxf((rn - 2.f * c0) + s_nn[c],     1e-12f);
                float d21 = fmaxf((rn - 2.f * c1) + s_nn[c + 1], 1e-12f);
                float2 o;
                o.x = 1.f / (1.f + sqrtf(d20));
                o.y = 1.f / (1.f + sqrtf(d21));
                *(float2*)(q + grow + c) = o;
                rsum += o.x + o.y;
                unsigned long long k0 = ukey(o.x, colBase + c);
                unsigned long long k1 = ukey(o.y, colBase + c + 1);
                if (k0 > rkey) rkey = k0;
                if (k1 > rkey) rkey = k1;
            }
            // reduce across the 4 tg lanes (lane = g4*4+tg; xor 1,2 stay in group)
            rsum += __shfl_xor_sync(0xFFFFFFFFu, rsum, 1);
            rsum += __shfl_xor_sync(0xFFFFFFFFu, rsum, 2);
            unsigned long long ok;
            ok = __shfl_xor_sync(0xFFFFFFFFu, rkey, 1); if (ok > rkey) rkey = ok;
            ok = __shfl_xor_sync(0xFFFFFFFFu, rkey, 2); if (ok > rkey) rkey = ok;
            if (tg == 0) {
                s_ps[wn * 128 + r] = rsum;
                s_pk[wn * 128 + r] = rkey;
            }
        }
    }
    __syncthreads();
    if (tid < 128) {
        float t = ((s_ps[tid] + s_ps[128 + tid]) + (s_ps[256 + tid] + s_ps[384 + tid]));
        unsigned long long k = s_pk[tid];
        if (s_pk[128 + tid] > k) k = s_pk[128 + tid];
        if (s_pk[256 + tid] > k) k = s_pk[256 + tid];
        if (s_pk[384 + tid] > k) k = s_pk[384 + tid];
        g_psum[(size_t)(rowBase + tid) * NTILE + ct] = t;
        g_pkey[(size_t)(rowBase + tid) * NTILE + ct] = k;
    }
}

// ---------------------------------------------------------------------------
// K2: streaming per-row pass. No block reductions: sum/argmax come from the
// GEMM's partials. Normalize q in place, fp64-exact argmin refinement for
// near-ties, som_z / bmu / k_coord.
// ---------------------------------------------------------------------------
__global__ __launch_bounds__(256) void k_row(const float* __restrict__ z,
                                             const float* __restrict__ mask,
                                             const float* __restrict__ nodes,
                                             float* __restrict__ out) {
    int r = blockIdx.x;
    int tid = threadIdx.x;
    int lane = tid & 31, warp = tid >> 5;
    float* qptr = out + OFF_Q + (size_t)r * Gv;

    __shared__ float sInv, sUt;
    __shared__ int   sBmu0;
    __shared__ int   sCand[MAX_CAND];
    __shared__ int   sCnt;
    __shared__ double sWd[8];
    __shared__ double sBest;

    if (tid == 0) {
        float s = 0.f;
        unsigned long long k = 0ull;
#pragma unroll
        for (int i = 0; i < NTILE; i++) {
            s += g_psum[(size_t)r * NTILE + i];
            unsigned long long kk = g_pkey[(size_t)r * NTILE + i];
            if (kk > k) k = kk;
        }
        sInv = 1.f / s;
        float umax = __uint_as_float((uint32_t)(k >> 32));
        float dist1 = 1.f / umax - 1.f;
        sUt = 1.f / (1.f + dist1 + REFINE_MARGIN);
        sBmu0 = Gv - 1 - (int)(uint32_t)(k & 0xFFFFFFFFull);
        sCnt = 0;
    }
    __syncthreads();
    float inv = sInv, ut = sUt;
    int bmu = sBmu0;

    float4 u4 = ((const float4*)qptr)[tid];
    // candidate detection on raw u
    {
        float uu[4] = {u4.x, u4.y, u4.z, u4.w};
#pragma unroll
        for (int j = 0; j < 4; j++) {
            if (uu[j] >= ut) {
                int slot = atomicAdd(&sCnt, 1);
                if (slot < MAX_CAND) sCand[slot] = tid * 4 + j;
            }
        }
    }
    u4.x *= inv; u4.y *= inv; u4.z *= inv; u4.w *= inv;
    ((float4*)qptr)[tid] = u4;
    __syncthreads();

    bool overflow = sCnt > MAX_CAND;
    int ncand = overflow ? Gv : sCnt;

    if (ncand > 1) {
        float wzv = g_wz[(size_t)r * Dv + tid];
        double bestd = 1e300;
        int besti = Gv;
        for (int c = 0; c < ncand; c++) {
            int g = overflow ? c : sCand[c];
            double diff = (double)wzv - (double)nodes[(size_t)g * Dv + tid];
            double d = diff * diff;
#pragma unroll
            for (int off = 16; off > 0; off >>= 1)
                d += __shfl_xor_sync(0xFFFFFFFFu, d, off);
            if (lane == 0) sWd[warp] = d;
            __syncthreads();
            if (tid == 0) {
                double s = 0.0;
#pragma unroll
                for (int w = 0; w < 8; w++) s += sWd[w];
                sBest = s;
            }
            __syncthreads();
            double d2c = sBest;
            if (d2c < bestd || (d2c == bestd && g < besti)) { bestd = d2c; besti = g; }
        }
        bmu = besti;
    }

    // som_z
    float zz = z[(size_t)r * Dv + tid];
    float m = mask[r];
    float nv = nodes[(size_t)bmu * Dv + tid];
    out[(size_t)r * Dv + tid] = zz + 0.1f * (nv - zz) * m;

    if (tid == 0) {
        out[OFF_BMU + r] = (float)bmu;
        float* kc = out + OFF_KC;
        kc[(size_t)r * 2 + 0] = (float)(bmu / GWv);
        kc[(size_t)r * 2 + 1] = (float)(bmu % GWv);
    }
}

// ---------------------------------------------------------------------------
extern "C" void kernel_launch(void* const* d_in, const int* in_sizes, int n_in,
                              void* d_out, int out_size) {
    (void)in_sizes; (void)n_in; (void)out_size;
    const float* z     = (const float*)d_in[0];
    const float* mask  = (const float*)d_in[1];
    const float* nodes = (const float*)d_in[2];
    float* out = (float*)d_out;

    k_node_norm<<<Gv, 128>>>(nodes);
    k_prep<<<BT / 8, 256>>>(z, mask);
    dim3 grid(BT / 128, Gv / 128);   // row-tile fast: contiguous q writes
    k_gemm_bf<<<grid, 512>>>(out);
    k_row<<<BT, 256>>>(z, mask, nodes, out);
}

// round 14
// speedup vs baseline: 1.0456x; 1.0456x over previous
#include <cuda_runtime.h>
#include <cuda_fp16.h>
#include <math.h>
#include <stdint.h>

// Problem constants (fixed by the dataset)
#define Bv 16
#define Tv 3072
#define Dv 256
#define GHv 32
#define GWv 32
#define Gv 1024
#define BT (Bv * Tv)          // 49152

// Output layout: concat of [som_z (BT*Dv)] [q (BT*Gv)] [bmu (BT)] [k_coord (BT*2)]
#define OFF_Q   ((size_t)BT * Dv)
#define OFF_BMU (OFF_Q + (size_t)BT * Gv)
#define OFF_KC  (OFF_BMU + (size_t)BT)

// Exact-argmin refinement margin (dist units) and candidate cap.
#define REFINE_MARGIN 1.5e-2f
#define MAX_CAND 64

// GEMM tiling: BM=128, BN=128, K chunks of 32
#define KCH 32
#define NCHUNK (Dv / KCH)      // 8

// Scratch (static device allocation — allowed; no cudaMalloc)
__device__ float    g_wz[(size_t)BT * Dv];    // weighted z, fp32 (refinement)
__device__ uint32_t g_wzh[(size_t)BT * 128];  // weighted z, bf16x2 kpairs (GEMM A)
__device__ uint32_t g_ndh[(size_t)Gv * 128];  // nodes, bf16x2 kpairs (GEMM B)
__device__ float    g_rown[BT];               // ||wz_row||^2
__device__ float    g_nn[Gv];                 // ||node||^2
__device__ uint32_t g_uh[(size_t)BT * (Gv / 2)];  // unnormalized u, fp16x2 (100 MB)

// ---------------------------------------------------------------------------
// helpers
// ---------------------------------------------------------------------------
__device__ __forceinline__ uint32_t bfpack(float lo, float hi) {
    uint32_t r;
    asm("cvt.rn.bf16x2.f32 %0, %1, %2;" : "=r"(r) : "f"(hi), "f"(lo));
    return r;
}

__device__ __forceinline__ uint32_t f16pack(float lo, float hi) {
    uint32_t r;
    asm("cvt.rn.f16x2.f32 %0, %1, %2;" : "=r"(r) : "f"(hi), "f"(lo));
    return r;
}

__device__ __forceinline__ void mma16(float* c, const uint32_t* a,
                                      uint32_t b0, uint32_t b1) {
    asm volatile(
        "mma.sync.aligned.m16n8k16.row.col.f32.bf16.bf16.f32 "
        "{%0,%1,%2,%3}, {%4,%5,%6,%7}, {%8,%9}, {%0,%1,%2,%3};"
        : "+f"(c[0]), "+f"(c[1]), "+f"(c[2]), "+f"(c[3])
        : "r"(a[0]), "r"(a[1]), "r"(a[2]), "r"(a[3]), "r"(b0), "r"(b1));
}

// Fragment-major word index for A (128 rows x 16 kpairs per chunk).
__device__ __forceinline__ int aIdx(int row, int p) {
    int wm = row >> 5, mi = (row >> 4) & 1, hi = (row >> 3) & 1, g4 = row & 7;
    int kk = p >> 3, w8 = p & 7, tg = w8 & 3, poff = w8 >> 2;
    return (((wm * 2 + mi) * 2 + kk) * 128) + g4 * 16 + tg * 4 + poff * 2 + hi;
}

// Fragment-major word index for B (128 n x 16 kpairs per chunk).
__device__ __forceinline__ int bIdx(int n, int p) {
    int wn = n >> 5, ni = (n >> 3) & 3, g4 = n & 7;
    int nh = ni >> 1, nl = ni & 1;
    int kk = p >> 3, w8 = p & 7, tg = w8 & 3, b01 = w8 >> 2;
    return ((wn * 2 + kk) * 256) + nh * 128 + g4 * 16 + tg * 4 + nl * 2 + b01;
}

// ---------------------------------------------------------------------------
// K0a: node norms + bf16 pack. 128 threads per node.
// ---------------------------------------------------------------------------
__global__ __launch_bounds__(128) void k_node_norm(const float* __restrict__ nodes) {
    int g = blockIdx.x;
    int tid = threadIdx.x;
    int lane = tid & 31, warp = tid >> 5;
    float2 v = ((const float2*)(nodes + (size_t)g * Dv))[tid];
    g_ndh[(size_t)g * 128 + tid] = bfpack(v.x, v.y);
    float s = v.x * v.x + v.y * v.y;
#pragma unroll
    for (int off = 16; off > 0; off >>= 1)
        s += __shfl_xor_sync(0xFFFFFFFFu, s, off);
    __shared__ float sw[4];
    if (lane == 0) sw[warp] = s;
    __syncthreads();
    if (tid == 0) g_nn[g] = (sw[0] + sw[1]) + (sw[2] + sw[3]);
}

// ---------------------------------------------------------------------------
// K0b: warp-per-row prep. wz (fp32 + bf16 pack) + row norms.
// ---------------------------------------------------------------------------
__global__ __launch_bounds__(256) void k_prep(const float* __restrict__ z,
                                              const float* __restrict__ mask) {
    int warp = threadIdx.x >> 5, lane = threadIdx.x & 31;
    int r = blockIdx.x * 8 + warp;
    float tw = 0.f;
    if (lane == 0) {
        int t = r % Tv;
        tw = powf(0.999f, (float)(Tv - 1 - t));
    }
    tw = __shfl_sync(0xFFFFFFFFu, tw, 0);
    float m = mask[r];
    const float* zp = z + (size_t)r * Dv + lane * 8;
    float* wp = g_wz + (size_t)r * Dv + lane * 8;
    float4 a = *(const float4*)zp;
    float4 b = *(const float4*)(zp + 4);
    a.x = (a.x * tw) * m; a.y = (a.y * tw) * m; a.z = (a.z * tw) * m; a.w = (a.w * tw) * m;
    b.x = (b.x * tw) * m; b.y = (b.y * tw) * m; b.z = (b.z * tw) * m; b.w = (b.w * tw) * m;
    *(float4*)wp = a;
    *(float4*)(wp + 4) = b;
    uint4 h;
    h.x = bfpack(a.x, a.y); h.y = bfpack(a.z, a.w);
    h.z = bfpack(b.x, b.y); h.w = bfpack(b.z, b.w);
    *(uint4*)(g_wzh + (size_t)r * 128 + lane * 4) = h;
    float s = a.x * a.x + a.y * a.y + a.z * a.z + a.w * a.w
            + b.x * b.x + b.y * b.y + b.z * b.z + b.w * b.w;
#pragma unroll
    for (int off = 16; off > 0; off >>= 1)
        s += __shfl_xor_sync(0xFFFFFFFFu, s, off);
    if (lane == 0) g_rown[r] = s;
}

// ---------------------------------------------------------------------------
// K1: bf16 mma.sync m16n8k16 GEMM on pre-packed operands, fragment-major
// smem, double-buffered. BM=128, BN=128, 512 threads (4M x 4N warps).
// grid = (BT/128, Gv/128), row-tile fast. Epilogue writes unnormalized u
// as fp16x2 into the g_uh scratch (halved write traffic).
// ---------------------------------------------------------------------------
__global__ __launch_bounds__(512, 2) void k_gemm_bf(float* __restrict__ out) {
    __shared__ uint32_t sA[2][2048];
    __shared__ uint32_t sB[2][2048];
    __shared__ float s_rn[128];
    __shared__ float s_nn[128];

    int tid = threadIdx.x;
    int lane = tid & 31, wid = tid >> 5;
    int g4 = lane >> 2, tg = lane & 3;
    int wm = wid & 3, wn = wid >> 2;
    int rowBase = blockIdx.x * 128;    // fast axis
    int colBase = blockIdx.y * 128;

    int lrow = tid >> 2;               // 0..127
    int s4 = (tid & 3) * 4;

    const uint32_t* Ag = g_wzh + (size_t)(rowBase + lrow) * 128 + s4;
    const uint32_t* Bg = g_ndh + (size_t)(colBase + lrow) * 128 + s4;

    int aI[4], bI[4];
#pragma unroll
    for (int j = 0; j < 4; j++) {
        aI[j] = aIdx(lrow, s4 + j);
        bI[j] = bIdx(lrow, s4 + j);
    }

    float acc[2][4][4];
#pragma unroll
    for (int mi = 0; mi < 2; mi++)
#pragma unroll
        for (int ni = 0; ni < 4; ni++)
#pragma unroll
            for (int k = 0; k < 4; k++) acc[mi][ni][k] = 0.f;

    uint4 pa = *(const uint4*)(Ag);
    uint4 pb = *(const uint4*)(Bg);

    {
        const uint32_t* aw = (const uint32_t*)&pa;
        const uint32_t* bw = (const uint32_t*)&pb;
#pragma unroll
        for (int j = 0; j < 4; j++) { sA[0][aI[j]] = aw[j]; sB[0][bI[j]] = bw[j]; }
    }
    __syncthreads();

    for (int ch = 0; ch < NCHUNK; ch++) {
        int cur = ch & 1;
        if (ch + 1 < NCHUNK) {
            pa = *(const uint4*)(Ag + (ch + 1) * 16);
            pb = *(const uint4*)(Bg + (ch + 1) * 16);
        }

#pragma unroll
        for (int kk = 0; kk < 2; kk++) {
            uint4 af[2], bv[2];
#pragma unroll
            for (int mi = 0; mi < 2; mi++)
                af[mi] = *(const uint4*)&sA[cur][((wm * 2 + mi) * 2 + kk) * 128 + g4 * 16 + tg * 4];
#pragma unroll
            for (int nh = 0; nh < 2; nh++)
                bv[nh] = *(const uint4*)&sB[cur][(wn * 2 + kk) * 256 + nh * 128 + g4 * 16 + tg * 4];
#pragma unroll
            for (int mi = 0; mi < 2; mi++) {
                const uint32_t* ar = (const uint32_t*)&af[mi];
                mma16(acc[mi][0], ar, bv[0].x, bv[0].y);
                mma16(acc[mi][1], ar, bv[0].z, bv[0].w);
                mma16(acc[mi][2], ar, bv[1].x, bv[1].y);
                mma16(acc[mi][3], ar, bv[1].z, bv[1].w);
            }
        }

        if (ch + 1 < NCHUNK) {
            int nb = 1 - cur;
            const uint32_t* aw = (const uint32_t*)&pa;
            const uint32_t* bw = (const uint32_t*)&pb;
#pragma unroll
            for (int j = 0; j < 4; j++) { sA[nb][aI[j]] = aw[j]; sB[nb][bI[j]] = bw[j]; }
            __syncthreads();
        }
    }

    if (tid < 128) {
        s_rn[tid] = g_rown[rowBase + tid];
        s_nn[tid] = g_nn[colBase + tid];
    }
    __syncthreads();

#pragma unroll
    for (int mi = 0; mi < 2; mi++) {
#pragma unroll
        for (int h = 0; h < 2; h++) {
            int r = wm * 32 + mi * 16 + g4 + h * 8;
            float rn = s_rn[r];
            size_t grow = (size_t)(rowBase + r) * (Gv / 2) + colBase / 2;
#pragma unroll
            for (int ni = 0; ni < 4; ni++) {
                int c = wn * 32 + ni * 8 + tg * 2;
                float c0 = acc[mi][ni][h * 2 + 0];
                float c1 = acc[mi][ni][h * 2 + 1];
                float d20 = fmaxf((rn - 2.f * c0) + s_nn[c],     1e-12f);
                float d21 = fmaxf((rn - 2.f * c1) + s_nn[c + 1], 1e-12f);
                float u0 = 1.f / (1.f + sqrtf(d20));
                float u1 = 1.f / (1.f + sqrtf(d21));
                g_uh[grow + c / 2] = f16pack(u0, u1);
            }
        }
    }
    (void)out;
}

// ---------------------------------------------------------------------------
// K2: per-row pass. Reads fp16 u (half the bytes), shuffle sum + argmax
// (tie -> lowest index), writes normalized fp32 q WRITE-ONLY, fp64 exact
// refinement of argmin for near-ties, som_z / bmu / k_coord.
// ---------------------------------------------------------------------------
__global__ __launch_bounds__(256) void k_row(const float* __restrict__ z,
                                             const float* __restrict__ mask,
                                             const float* __restrict__ nodes,
                                             float* __restrict__ out) {
    int r = blockIdx.x;
    int tid = threadIdx.x;
    int lane = tid & 31, warp = tid >> 5;
    float* qptr = out + OFF_Q + (size_t)r * Gv;

    uint2 hw = ((const uint2*)(g_uh + (size_t)r * (Gv / 2)))[tid];
    float2 lo = __half22float2(*(half2*)&hw.x);
    float2 hi = __half22float2(*(half2*)&hw.y);
    float4 u4;
    u4.x = lo.x; u4.y = lo.y; u4.z = hi.x; u4.w = hi.y;
    float4 uo = u4;

    float lsum = (u4.x + u4.y) + (u4.z + u4.w);
    float bv = u4.x; int bi = tid * 4;
    if (u4.y > bv) { bv = u4.y; bi = tid * 4 + 1; }
    if (u4.z > bv) { bv = u4.z; bi = tid * 4 + 2; }
    if (u4.w > bv) { bv = u4.w; bi = tid * 4 + 3; }

#pragma unroll
    for (int off = 16; off > 0; off >>= 1) {
        float os = __shfl_xor_sync(0xFFFFFFFFu, lsum, off);
        float ov = __shfl_xor_sync(0xFFFFFFFFu, bv, off);
        int   oi = __shfl_xor_sync(0xFFFFFFFFu, bi, off);
        lsum += os;
        if (ov > bv || (ov == bv && oi < bi)) { bv = ov; bi = oi; }
    }

    __shared__ float sWs[8], sWv[8];
    __shared__ int   sWi[8];
    __shared__ float sSum, sMax;
    __shared__ int   sBmu;
    if (lane == 0) { sWs[warp] = lsum; sWv[warp] = bv; sWi[warp] = bi; }
    __syncthreads();
    if (tid == 0) {
        float ts = 0.f, tv = -1.f; int ti = 0;
#pragma unroll
        for (int w = 0; w < 8; w++) {
            ts += sWs[w];
            if (sWv[w] > tv || (sWv[w] == tv && sWi[w] < ti)) { tv = sWv[w]; ti = sWi[w]; }
        }
        sSum = ts; sMax = tv; sBmu = ti;
    }
    __syncthreads();
    float inv = 1.f / sSum;
    float umax = sMax;
    int bmu = sBmu;

    // q write-only (scratch holds u; q region never read)
    u4.x *= inv; u4.y *= inv; u4.z *= inv; u4.w *= inv;
    ((float4*)qptr)[tid] = u4;

    // ---- exact argmin refinement for near-ties ----
    float dist1 = 1.f / umax - 1.f;
    float ut = 1.f / (1.f + dist1 + REFINE_MARGIN);

    __shared__ int sCand[MAX_CAND];
    __shared__ int sCnt;
    __shared__ double sWd[8];
    __shared__ double sBest;
    if (tid == 0) sCnt = 0;
    __syncthreads();
    {
        float uu[4] = {uo.x, uo.y, uo.z, uo.w};
#pragma unroll
        for (int j = 0; j < 4; j++) {
            if (uu[j] >= ut) {
                int slot = atomicAdd(&sCnt, 1);
                if (slot < MAX_CAND) sCand[slot] = tid * 4 + j;
            }
        }
    }
    __syncthreads();
    bool overflow = sCnt > MAX_CAND;
    int ncand = overflow ? Gv : sCnt;

    if (ncand > 1) {
        float wzv = g_wz[(size_t)r * Dv + tid];
        double bestd = 1e300;
        int besti = Gv;
        for (int c = 0; c < ncand; c++) {
            int g = overflow ? c : sCand[c];
            double diff = (double)wzv - (double)nodes[(size_t)g * Dv + tid];
            double d = diff * diff;
#pragma unroll
            for (int off = 16; off > 0; off >>= 1)
                d += __shfl_xor_sync(0xFFFFFFFFu, d, off);
            if (lane == 0) sWd[warp] = d;
            __syncthreads();
            if (tid == 0) {
                double s = 0.0;
#pragma unroll
                for (int w = 0; w < 8; w++) s += sWd[w];
                sBest = s;
            }
            __syncthreads();
            double d2c = sBest;
            if (d2c < bestd || (d2c == bestd && g < besti)) { bestd = d2c; besti = g; }
        }
        bmu = besti;
    }

    // som_z
    float zz = z[(size_t)r * Dv + tid];
    float m = mask[r];
    float nv = nodes[(size_t)bmu * Dv + tid];
    out[(size_t)r * Dv + tid] = zz + 0.1f * (nv - zz) * m;

    if (tid == 0) {
        out[OFF_BMU + r] = (float)bmu;
        float* kc = out + OFF_KC;
        kc[(size_t)r * 2 + 0] = (float)(bmu / GWv);
        kc[(size_t)r * 2 + 1] = (float)(bmu % GWv);
    }
}

// ---------------------------------------------------------------------------
extern "C" void kernel_launch(void* const* d_in, const int* in_sizes, int n_in,
                              void* d_out, int out_size) {
    (void)in_sizes; (void)n_in; (void)out_size;
    const float* z     = (const float*)d_in[0];
    const float* mask  = (const float*)d_in[1];
    const float* nodes = (const float*)d_in[2];
    float* out = (float*)d_out;

    k_node_norm<<<Gv, 128>>>(nodes);
    k_prep<<<BT / 8, 256>>>(z, mask);
    dim3 grid(BT / 128, Gv / 128);   // row-tile fast
    k_gemm_bf<<<grid, 512>>>(out);
    k_row<<<BT, 256>>>(z, mask, nodes, out);
}